// round 11
// baseline (speedup 1.0000x reference)
#include <cuda_runtime.h>
#include <cstdint>

#define NN 100000
#define NP 100032              // padded to multiple of 64
#define EE 800000
#define NB (NP / 64)           // 1563 blocks of 64 rows

// ---------------- scratch (device globals; no allocation allowed) ----------
__device__ float g_h0[NP * 128];
__device__ float g_h1[NP * 128];
__device__ float g_nh0[NP * 128];
__device__ float g_nh1[NP * 128];
__device__ float g_A[4][NN * 16];        // per-dst sum of raw edge attrs
__device__ int   g_deg[4][NN];
__device__ int   g_rowstart[4][NN + 1];
__device__ int   g_cursor[4][NN];
__device__ int   g_csrc[4][EE];          // CSR: src node per slot
__device__ int   g_ceid[4][EE];          // CSR: edge id per slot
__device__ float g_stats[2][256];        // [node type][ sum(128) | sumsq(128) ]
__device__ float g_bnp[2][2][128];       // [node type][ scale | shift ]

// ---------------- tf32 MMA helpers -----------------------------------------
__device__ __forceinline__ float to_tf32(float x) {
    uint32_t u;
    asm("cvt.rna.tf32.f32 %0, %1;" : "=r"(u) : "f"(x));
    return __uint_as_float(u);
}

__device__ __forceinline__ void mma_tf32(float (&d)[4], const uint32_t (&a)[4],
                                         const uint32_t (&b)[2]) {
    asm volatile(
        "mma.sync.aligned.m16n8k8.row.col.f32.tf32.tf32.f32 "
        "{%0,%1,%2,%3}, {%4,%5,%6,%7}, {%8,%9}, {%0,%1,%2,%3};"
        : "+f"(d[0]), "+f"(d[1]), "+f"(d[2]), "+f"(d[3])
        : "r"(a[0]), "r"(a[1]), "r"(a[2]), "r"(a[3]), "r"(b[0]), "r"(b[1]));
}

// A fragment from row-major smem [row][k], stride S (floats). S mod 32 == 4.
__device__ __forceinline__ void lda_frag(uint32_t (&af)[4], const float* sA, int S,
                                         int rbase, int k0, int lane) {
    const float* p = sA + (rbase + (lane >> 2)) * S + k0 + (lane & 3);
    af[0] = __float_as_uint(p[0]);
    af[1] = __float_as_uint(p[8 * S]);
    af[2] = __float_as_uint(p[4]);
    af[3] = __float_as_uint(p[8 * S + 4]);
}

// B fragment from smem [k][n], stride S (floats).
__device__ __forceinline__ void ldb_frag(uint32_t (&bf)[2], const float* sB, int S,
                                         int k0, int n0, int lane) {
    const float* q = sB + (k0 + (lane & 3)) * S + n0 + (lane >> 2);
    bf[0] = __float_as_uint(q[0]);
    bf[1] = __float_as_uint(q[4 * S]);
}

__device__ __forceinline__ float4 bn_relu4(float4 v, float4 sc, float4 sh) {
    v.x = fmaxf(fmaf(v.x, sc.x, sh.x), 0.f);
    v.y = fmaxf(fmaf(v.y, sc.y, sh.y), 0.f);
    v.z = fmaxf(fmaf(v.z, sc.z, sh.z), 0.f);
    v.w = fmaxf(fmaf(v.w, sc.w, sh.w), 0.f);
    return v;
}

__device__ __forceinline__ void st_tf32x4(float* d, float4 v) {
    d[0] = to_tf32(v.x); d[1] = to_tf32(v.y);
    d[2] = to_tf32(v.z); d[3] = to_tf32(v.w);
}

// Gather one aggregation row: deg*be + A@We + sum f(h_src). Warp-collective,
// lane owns cols [lane*4, lane*4+4). sWe = 16x128 weights in smem.
template<bool L1>
__device__ __forceinline__ float4 gather_row(int t, int dst,
                                             const float* __restrict__ src,
                                             const float* sWe, float4 be4,
                                             float4 sc4, float4 sh4, int lane) {
    int c0 = lane * 4;
    int rs = g_rowstart[t][dst], re = g_rowstart[t][dst + 1];
    float degf = (float)(re - rs);
    float4 acc = make_float4(degf * be4.x, degf * be4.y, degf * be4.z, degf * be4.w);
    const float* __restrict__ aP = &g_A[t][dst * 16];
#pragma unroll
    for (int k = 0; k < 16; k++) {
        float a = aP[k];
        float4 w = *(const float4*)(sWe + k * 128 + c0);
        acc.x += a * w.x; acc.y += a * w.y; acc.z += a * w.z; acc.w += a * w.w;
    }
    const int* __restrict__ srcp = g_csrc[t];
    const float4* __restrict__ H4 = (const float4*)src;
    float4 accB = make_float4(0.f, 0.f, 0.f, 0.f);
    int e = rs;
    for (; e + 4 <= re; e += 4) {
        int s0 = srcp[e], s1 = srcp[e + 1], s2 = srcp[e + 2], s3 = srcp[e + 3];
        float4 v0 = H4[s0 * 32 + lane];
        float4 v1 = H4[s1 * 32 + lane];
        float4 v2 = H4[s2 * 32 + lane];
        float4 v3 = H4[s3 * 32 + lane];
        if (L1) {
            v0 = bn_relu4(v0, sc4, sh4); v1 = bn_relu4(v1, sc4, sh4);
            v2 = bn_relu4(v2, sc4, sh4); v3 = bn_relu4(v3, sc4, sh4);
        }
        acc.x += v0.x + v2.x; acc.y += v0.y + v2.y;
        acc.z += v0.z + v2.z; acc.w += v0.w + v2.w;
        accB.x += v1.x + v3.x; accB.y += v1.y + v3.y;
        accB.z += v1.z + v3.z; accB.w += v1.w + v3.w;
    }
    for (; e < re; e++) {
        float4 v = H4[srcp[e] * 32 + lane];
        if (L1) v = bn_relu4(v, sc4, sh4);
        acc.x += v.x; acc.y += v.y; acc.z += v.z; acc.w += v.w;
    }
    acc.x += accB.x; acc.y += accB.y; acc.z += accB.z; acc.w += accB.w;
    return acc;
}

// ---------------- CSR build ------------------------------------------------
__global__ void hist_kernel(const int* __restrict__ e0, const int* __restrict__ e1,
                            const int* __restrict__ e2, const int* __restrict__ e3) {
    int t = blockIdx.y;
    const int* ei = (t == 0) ? e0 : (t == 1) ? e1 : (t == 2) ? e2 : e3;
    int e = blockIdx.x * blockDim.x + threadIdx.x;
    if (e < EE) atomicAdd(&g_deg[t][ei[EE + e]], 1);
}

__global__ void scan_kernel() {
    int t = blockIdx.x;
    __shared__ int sp[1024];
    int tid = threadIdx.x;
    const int chunk = (NN + 1023) / 1024;
    int start = tid * chunk;
    int end = start + chunk; if (end > NN) end = NN;
    int s = 0;
    for (int i = start; i < end; i++) s += g_deg[t][i];
    sp[tid] = s;
    __syncthreads();
    for (int off = 1; off < 1024; off <<= 1) {
        int v = (tid >= off) ? sp[tid - off] : 0;
        __syncthreads();
        sp[tid] += v;
        __syncthreads();
    }
    int run = sp[tid] - s;
    for (int i = start; i < end; i++) {
        g_rowstart[t][i] = run;
        g_cursor[t][i] = run;
        run += g_deg[t][i];
    }
    if (tid == 0) g_rowstart[t][NN] = EE;
}

__global__ void fill_kernel(const int* __restrict__ e0, const int* __restrict__ e1,
                            const int* __restrict__ e2, const int* __restrict__ e3) {
    int t = blockIdx.y;
    const int* ei = (t == 0) ? e0 : (t == 1) ? e1 : (t == 2) ? e2 : e3;
    int e = blockIdx.x * blockDim.x + threadIdx.x;
    if (e >= EE) return;
    int dst = ei[EE + e];
    int slot = atomicAdd(&g_cursor[t][dst], 1);
    g_csrc[t][slot] = ei[e];
    g_ceid[t][slot] = e;
}

// Per-dst sum of raw 16-dim edge attrs (layer-invariant). Half-warp per dst.
__global__ __launch_bounds__(256) void ea_agg_kernel(const float* __restrict__ a0,
                                                     const float* __restrict__ a1,
                                                     const float* __restrict__ a2,
                                                     const float* __restrict__ a3) {
    int t = blockIdx.y;
    const float* ea = (t == 0) ? a0 : (t == 1) ? a1 : (t == 2) ? a2 : a3;
    int lane = threadIdx.x & 31;
    int warp = threadIdx.x >> 5;
    int sub = lane >> 4;
    int l16 = lane & 15;
    int dst = blockIdx.x * 16 + warp * 2 + sub;
    if (dst >= NN) return;
    const int* __restrict__ ceid = g_ceid[t];
    int rs = g_rowstart[t][dst], re = g_rowstart[t][dst + 1];
    float acc = 0.f, accB = 0.f;
    int e = rs;
    for (; e + 4 <= re; e += 4) {
        int e0 = ceid[e], e1 = ceid[e + 1], e2 = ceid[e + 2], e3 = ceid[e + 3];
        float v0 = ea[e0 * 16 + l16];
        float v1 = ea[e1 * 16 + l16];
        float v2 = ea[e2 * 16 + l16];
        float v3 = ea[e3 * 16 + l16];
        acc += v0 + v2;
        accB += v1 + v3;
    }
    for (; e < re; e++) acc += ea[ceid[e] * 16 + l16];
    g_A[t][dst * 16 + l16] = acc + accB;
}

// ---------------- embed: H = X @ Wx + bx  (M=NP tiles of 64, K=256, N=128) --
__global__ __launch_bounds__(256) void embed_tc(const float* __restrict__ X,
                                                const float* __restrict__ W,
                                                const float* __restrict__ bx,
                                                float* __restrict__ H) {
    __shared__ float sA[64 * 68];    // 64 rows x 64 k, pad 4
    __shared__ float sB[64 * 136];   // 64 k x 128 n, pad 8
    int tid = threadIdx.x, lane = tid & 31, wid = tid >> 5;
    int wm = wid >> 2, wn = wid & 3;
    int row0 = blockIdx.x * 64;
    float acc[2][4][4] = {};
    float4 pa[4], pb[8];

#pragma unroll
    for (int j = 0; j < 4; j++) {
        int i = tid + j * 256, r = i >> 4, c4 = (i & 15) * 4;
        pa[j] = make_float4(0.f, 0.f, 0.f, 0.f);
        if (row0 + r < NN)
            pa[j] = *(const float4*)(X + (size_t)(row0 + r) * 256 + c4);
    }
#pragma unroll
    for (int j = 0; j < 8; j++) {
        int i = tid + j * 256, r = i >> 5, c4 = (i & 31) * 4;
        pb[j] = *(const float4*)(W + (size_t)r * 128 + c4);
    }

    for (int kc = 0; kc < 4; kc++) {
        __syncthreads();
#pragma unroll
        for (int j = 0; j < 4; j++) {
            int i = tid + j * 256, r = i >> 4, c4 = (i & 15) * 4;
            st_tf32x4(sA + r * 68 + c4, pa[j]);
        }
#pragma unroll
        for (int j = 0; j < 8; j++) {
            int i = tid + j * 256, r = i >> 5, c4 = (i & 31) * 4;
            st_tf32x4(sB + r * 136 + c4, pb[j]);
        }
        __syncthreads();
        if (kc < 3) {
            int kn = kc + 1;
#pragma unroll
            for (int j = 0; j < 4; j++) {
                int i = tid + j * 256, r = i >> 4, c4 = (i & 15) * 4;
                pa[j] = make_float4(0.f, 0.f, 0.f, 0.f);
                if (row0 + r < NN)
                    pa[j] = *(const float4*)(X + (size_t)(row0 + r) * 256 + kn * 64 + c4);
            }
#pragma unroll
            for (int j = 0; j < 8; j++) {
                int i = tid + j * 256, r = i >> 5, c4 = (i & 31) * 4;
                pb[j] = *(const float4*)(W + (size_t)(kn * 64 + r) * 128 + c4);
            }
        }
#pragma unroll
        for (int ks = 0; ks < 8; ks++) {
            int k0 = ks * 8;
            uint32_t bf[4][2];
#pragma unroll
            for (int nt = 0; nt < 4; nt++)
                ldb_frag(bf[nt], sB, 136, k0, wn * 32 + nt * 8, lane);
#pragma unroll
            for (int mt = 0; mt < 2; mt++) {
                uint32_t af[4];
                lda_frag(af, sA, 68, wm * 32 + mt * 16, k0, lane);
#pragma unroll
                for (int nt = 0; nt < 4; nt++) mma_tf32(acc[mt][nt], af, bf[nt]);
            }
        }
    }
#pragma unroll
    for (int mt = 0; mt < 2; mt++)
#pragma unroll
        for (int nt = 0; nt < 4; nt++) {
            int r = row0 + wm * 32 + mt * 16 + (lane >> 2);
            int c = wn * 32 + nt * 8 + (lane & 3) * 2;
            float b0 = bx[c], b1 = bx[c + 1];
            *(float2*)(H + (size_t)r * 128 + c) =
                make_float2(acc[mt][nt][0] + b0, acc[mt][nt][1] + b1);
            *(float2*)(H + (size_t)(r + 8) * 128 + c) =
                make_float2(acc[mt][nt][2] + b0, acc[mt][nt][3] + b1);
        }
}

// ---------------- combine0 (fused gather): out0 rows of node type '0' -------
// out0 = 0.05*( agg10@W10 + agg00@W00 + b10 + b00 ), aggs gathered in-kernel.
// smem: sA 64x260 (K=256 A tile), sB 64x136 (weight chunks / We during gather)
template<bool L1>
__global__ __launch_bounds__(256, 2) void combine0_tc(const float* __restrict__ W10,
                                                      const float* __restrict__ b10,
                                                      const float* __restrict__ W00,
                                                      const float* __restrict__ b00,
                                                      const float* __restrict__ src1,
                                                      const float* __restrict__ src0,
                                                      const float* __restrict__ bnp1,
                                                      const float* __restrict__ bnp0,
                                                      const float* __restrict__ We,
                                                      const float* __restrict__ be,
                                                      float* __restrict__ out0) {
    extern __shared__ float dsm[];
    float* sA = dsm;              // 64*260 = 16640
    float* sB = dsm + 16640;      // 64*136 = 8704
    int tid = threadIdx.x, lane = tid & 31, wid = tid >> 5;
    int wm = wid >> 2, wn = wid & 3;
    int row0 = blockIdx.x * 64;
    int c0 = lane * 4;

    // stage We into sB (free until GEMM weight staging)
    for (int i = tid; i < 2048; i += 256) sB[i] = We[i];
    __syncthreads();

    float4 be4 = *(const float4*)(be + c0);
    float4 sc1 = make_float4(0, 0, 0, 0), sh1 = sc1, sc0 = sc1, sh0 = sc1;
    if (L1) {
        sc1 = *(const float4*)(bnp1 + c0); sh1 = *(const float4*)(bnp1 + 128 + c0);
        sc0 = *(const float4*)(bnp0 + c0); sh0 = *(const float4*)(bnp0 + 128 + c0);
    }

    // gather both aggregation types into the 64x256 A tile
    for (int i = 0; i < 8; i++) {
        int row = wid * 8 + i;
        int dst = row0 + row;
        float4 a2 = make_float4(0, 0, 0, 0), a3 = a2;
        if (dst < NN) {
            a2 = gather_row<L1>(2, dst, src1, sB, be4, sc1, sh1, lane);
            a3 = gather_row<L1>(3, dst, src0, sB, be4, sc0, sh0, lane);
        }
        st_tf32x4(sA + row * 260 + c0, a2);
        st_tf32x4(sA + row * 260 + 128 + c0, a3);
    }

    // GEMM over K=256 with double-buffered weight chunks
    float acc[2][4][4] = {};
    float4 pb[8];
#pragma unroll
    for (int j = 0; j < 8; j++) {
        int i = tid + j * 256, r = i >> 5, c4 = (i & 31) * 4;
        pb[j] = *(const float4*)(W10 + (size_t)r * 128 + c4);
    }
    for (int kc = 0; kc < 4; kc++) {
        __syncthreads();
#pragma unroll
        for (int j = 0; j < 8; j++) {
            int i = tid + j * 256, r = i >> 5, c4 = (i & 31) * 4;
            st_tf32x4(sB + r * 136 + c4, pb[j]);
        }
        __syncthreads();
        if (kc < 3) {
            int kn = kc + 1;
            const float* Wsrc = (kn < 2) ? W10 : W00;
            int kb = (kn & 1) * 64;
#pragma unroll
            for (int j = 0; j < 8; j++) {
                int i = tid + j * 256, r = i >> 5, c4 = (i & 31) * 4;
                pb[j] = *(const float4*)(Wsrc + (size_t)(kb + r) * 128 + c4);
            }
        }
#pragma unroll
        for (int ks = 0; ks < 8; ks++) {
            int k0g = kc * 64 + ks * 8, k0l = ks * 8;
            uint32_t bf[4][2];
#pragma unroll
            for (int nt = 0; nt < 4; nt++)
                ldb_frag(bf[nt], sB, 136, k0l, wn * 32 + nt * 8, lane);
#pragma unroll
            for (int mt = 0; mt < 2; mt++) {
                uint32_t af[4];
                lda_frag(af, sA, 260, wm * 32 + mt * 16, k0g, lane);
#pragma unroll
                for (int nt = 0; nt < 4; nt++) mma_tf32(acc[mt][nt], af, bf[nt]);
            }
        }
    }
    // epilogue + fused BN stats
#pragma unroll
    for (int nt = 0; nt < 4; nt++) {
        int c = wn * 32 + nt * 8 + (lane & 3) * 2;
        float b0 = b10[c] + b00[c], b1 = b10[c + 1] + b00[c + 1];
        float s0 = 0.f, s1 = 0.f, q0 = 0.f, q1 = 0.f;
#pragma unroll
        for (int mt = 0; mt < 2; mt++) {
            int r = row0 + wm * 32 + mt * 16 + (lane >> 2);
            float f0 = 0.05f * (acc[mt][nt][0] + b0);
            float f1 = 0.05f * (acc[mt][nt][1] + b1);
            float f2 = 0.05f * (acc[mt][nt][2] + b0);
            float f3 = 0.05f * (acc[mt][nt][3] + b1);
            *(float2*)(out0 + (size_t)r * 128 + c) = make_float2(f0, f1);
            *(float2*)(out0 + (size_t)(r + 8) * 128 + c) = make_float2(f2, f3);
            if (r < NN)     { s0 += f0; q0 += f0 * f0; s1 += f1; q1 += f1 * f1; }
            if (r + 8 < NN) { s0 += f2; q0 += f2 * f2; s1 += f3; q1 += f3 * f3; }
        }
#pragma unroll
        for (int off = 4; off < 32; off <<= 1) {
            s0 += __shfl_down_sync(0xffffffffu, s0, off);
            s1 += __shfl_down_sync(0xffffffffu, s1, off);
            q0 += __shfl_down_sync(0xffffffffu, q0, off);
            q1 += __shfl_down_sync(0xffffffffu, q1, off);
        }
        if ((lane >> 2) == 0) {
            atomicAdd(&g_stats[0][c], s0);
            atomicAdd(&g_stats[0][c + 1], s1);
            atomicAdd(&g_stats[0][128 + c], q0);
            atomicAdd(&g_stats[0][128 + c + 1], q1);
        }
    }
}

// ---------------- combine1 (fused gather): out1 rows of node type '1' -------
// out1 = 0.5*( relu((agg11+1.1*f(self))@gW1+gb1)@gW2+gb2 + 0.1*(agg01@W01+b01) )
// Order: gather agg01 -> phase3 -> stash l01 to out1 -> gather agg11+self ->
// phases 1&2 (two 128-col halves) -> final epilogue (readback stash).
// smem: sS 64x132, sU 64x132 (We lives in sU[0:2048] during gathers), sB 64x136
template<bool L1>
__global__ __launch_bounds__(256, 2) void combine1_tc(const float* __restrict__ gW1,
                                                      const float* __restrict__ gb1,
                                                      const float* __restrict__ gW2,
                                                      const float* __restrict__ gb2,
                                                      const float* __restrict__ W01,
                                                      const float* __restrict__ b01,
                                                      const float* __restrict__ src1,
                                                      const float* __restrict__ src0,
                                                      const float* __restrict__ bnp1,
                                                      const float* __restrict__ bnp0,
                                                      const float* __restrict__ We,
                                                      const float* __restrict__ be,
                                                      float* __restrict__ out1) {
    extern __shared__ float dsm[];
    float* sS = dsm;                  // 64*132 = 8448
    float* sU = dsm + 8448;           // 64*132 = 8448
    float* sB = dsm + 16896;          // 64*136 = 8704
    int tid = threadIdx.x, lane = tid & 31, wid = tid >> 5;
    int wm = wid >> 2, wn = wid & 3;
    int row0 = blockIdx.x * 64;
    int c0 = lane * 4;

    // stage We into sU (free until phase-1 epilogue)
    for (int i = tid; i < 2048; i += 256) sU[i] = We[i];
    __syncthreads();

    float4 be4 = *(const float4*)(be + c0);
    float4 sc1 = make_float4(0, 0, 0, 0), sh1 = sc1, sc0 = sc1, sh0 = sc1;
    if (L1) {
        sc1 = *(const float4*)(bnp1 + c0); sh1 = *(const float4*)(bnp1 + 128 + c0);
        sc0 = *(const float4*)(bnp0 + c0); sh0 = *(const float4*)(bnp0 + 128 + c0);
    }

    // ---- gather agg01 (type 1, src type 0) into sS ----
    for (int i = 0; i < 8; i++) {
        int row = wid * 8 + i;
        int dst = row0 + row;
        float4 a = make_float4(0, 0, 0, 0);
        if (dst < NN) a = gather_row<L1>(1, dst, src0, sU, be4, sc0, sh0, lane);
        st_tf32x4(sS + row * 132 + c0, a);
    }
    __syncthreads();

    // ---- phase 3: l01 = sS @ W01, stash 0.1*(l01+b01) into out1 ----
    {
        float4 pb[8];
#pragma unroll
        for (int j = 0; j < 8; j++) {
            int i = tid + j * 256, r = i >> 5, c4 = (i & 31) * 4;
            pb[j] = *(const float4*)(W01 + (size_t)r * 128 + c4);
        }
        float acc3[2][4][4] = {};
        for (int kc = 0; kc < 2; kc++) {
            __syncthreads();
#pragma unroll
            for (int j = 0; j < 8; j++) {
                int i = tid + j * 256, r = i >> 5, c4 = (i & 31) * 4;
                st_tf32x4(sB + r * 136 + c4, pb[j]);
            }
            __syncthreads();
            if (kc < 1) {
#pragma unroll
                for (int j = 0; j < 8; j++) {
                    int i = tid + j * 256, r = i >> 5, c4 = (i & 31) * 4;
                    pb[j] = *(const float4*)(W01 + (size_t)(64 + r) * 128 + c4);
                }
            }
#pragma unroll
            for (int ks = 0; ks < 8; ks++) {
                int k0g = kc * 64 + ks * 8, k0l = ks * 8;
                uint32_t bf[4][2];
#pragma unroll
                for (int nt = 0; nt < 4; nt++)
                    ldb_frag(bf[nt], sB, 136, k0l, wn * 32 + nt * 8, lane);
#pragma unroll
                for (int mt = 0; mt < 2; mt++) {
                    uint32_t af[4];
                    lda_frag(af, sS, 132, wm * 32 + mt * 16, k0g, lane);
#pragma unroll
                    for (int nt = 0; nt < 4; nt++) mma_tf32(acc3[mt][nt], af, bf[nt]);
                }
            }
        }
#pragma unroll
        for (int mt = 0; mt < 2; mt++)
#pragma unroll
            for (int nt = 0; nt < 4; nt++) {
                int r = row0 + wm * 32 + mt * 16 + (lane >> 2);
                int c = wn * 32 + nt * 8 + (lane & 3) * 2;
                float l0 = b01[c], l1 = b01[c + 1];
                *(float2*)(out1 + (size_t)r * 128 + c) =
                    make_float2(0.1f * (acc3[mt][nt][0] + l0), 0.1f * (acc3[mt][nt][1] + l1));
                *(float2*)(out1 + (size_t)(r + 8) * 128 + c) =
                    make_float2(0.1f * (acc3[mt][nt][2] + l0), 0.1f * (acc3[mt][nt][3] + l1));
            }
    }
    __syncthreads();   // phase-3 MMAs done before sS overwrite

    // ---- gather agg11 (type 0, src type 1) + 1.1*f(self) into sS ----
    for (int i = 0; i < 8; i++) {
        int row = wid * 8 + i;
        int dst = row0 + row;
        float4 a = make_float4(0, 0, 0, 0);
        if (dst < NN) {
            a = gather_row<L1>(0, dst, src1, sU, be4, sc1, sh1, lane);
            float4 self = *(const float4*)(src1 + (size_t)dst * 128 + c0);
            if (L1) self = bn_relu4(self, sc1, sh1);
            a.x += 1.1f * self.x; a.y += 1.1f * self.y;
            a.z += 1.1f * self.z; a.w += 1.1f * self.w;
        }
        st_tf32x4(sS + row * 132 + c0, a);
    }
    __syncthreads();

    // ---- phases 1 & 2: two 128-col halves of the GIN intermediate ----
    float acc2[2][4][4] = {};
    for (int nh = 0; nh < 2; nh++) {
        float4 pb1[4];
#pragma unroll
        for (int j = 0; j < 4; j++) {
            int i = tid + j * 256, r = i >> 5, c4 = (i & 31) * 4;
            pb1[j] = *(const float4*)(gW1 + (size_t)r * 256 + nh * 128 + c4);
        }
        float acc1[2][4][4] = {};
        for (int kc = 0; kc < 4; kc++) {
            __syncthreads();
#pragma unroll
            for (int j = 0; j < 4; j++) {
                int i = tid + j * 256, r = i >> 5, c4 = (i & 31) * 4;
                st_tf32x4(sB + r * 136 + c4, pb1[j]);
            }
            __syncthreads();
            if (kc < 3) {
                int kn = kc + 1;
#pragma unroll
                for (int j = 0; j < 4; j++) {
                    int i = tid + j * 256, r = i >> 5, c4 = (i & 31) * 4;
                    pb1[j] = *(const float4*)(gW1 + (size_t)(kn * 32 + r) * 256 + nh * 128 + c4);
                }
            }
#pragma unroll
            for (int ks = 0; ks < 4; ks++) {
                int k0g = kc * 32 + ks * 8, k0l = ks * 8;
                uint32_t bf[4][2];
#pragma unroll
                for (int nt = 0; nt < 4; nt++)
                    ldb_frag(bf[nt], sB, 136, k0l, wn * 32 + nt * 8, lane);
#pragma unroll
                for (int mt = 0; mt < 2; mt++) {
                    uint32_t af[4];
                    lda_frag(af, sS, 132, wm * 32 + mt * 16, k0g, lane);
#pragma unroll
                    for (int nt = 0; nt < 4; nt++) mma_tf32(acc1[mt][nt], af, bf[nt]);
                }
            }
        }
        __syncthreads();
#pragma unroll
        for (int mt = 0; mt < 2; mt++)
#pragma unroll
            for (int nt = 0; nt < 4; nt++) {
                int r = wm * 32 + mt * 16 + (lane >> 2);
                int c = wn * 32 + nt * 8 + (lane & 3) * 2;
                int cg = nh * 128 + c;
                float b0 = gb1[cg], b1 = gb1[cg + 1];
                float v0 = acc1[mt][nt][0] + b0; v0 = v0 > 0.f ? v0 : 0.f;
                float v1 = acc1[mt][nt][1] + b1; v1 = v1 > 0.f ? v1 : 0.f;
                float v2 = acc1[mt][nt][2] + b0; v2 = v2 > 0.f ? v2 : 0.f;
                float v3 = acc1[mt][nt][3] + b1; v3 = v3 > 0.f ? v3 : 0.f;
                sU[r * 132 + c] = to_tf32(v0);
                sU[r * 132 + c + 1] = to_tf32(v1);
                sU[(r + 8) * 132 + c] = to_tf32(v2);
                sU[(r + 8) * 132 + c + 1] = to_tf32(v3);
            }
        __syncthreads();

        float4 pb2[8];
#pragma unroll
        for (int j = 0; j < 8; j++) {
            int i = tid + j * 256, r = i >> 5, c4 = (i & 31) * 4;
            pb2[j] = *(const float4*)(gW2 + (size_t)(nh * 128 + r) * 128 + c4);
        }
        for (int kc2 = 0; kc2 < 2; kc2++) {
            __syncthreads();
#pragma unroll
            for (int j = 0; j < 8; j++) {
                int i = tid + j * 256, r = i >> 5, c4 = (i & 31) * 4;
                st_tf32x4(sB + r * 136 + c4, pb2[j]);
            }
            __syncthreads();
            if (kc2 < 1) {
#pragma unroll
                for (int j = 0; j < 8; j++) {
                    int i = tid + j * 256, r = i >> 5, c4 = (i & 31) * 4;
                    pb2[j] = *(const float4*)(gW2 + (size_t)(nh * 128 + 64 + r) * 128 + c4);
                }
            }
#pragma unroll
            for (int ks = 0; ks < 8; ks++) {
                int k0u = kc2 * 64 + ks * 8, k0l = ks * 8;
                uint32_t bf[4][2];
#pragma unroll
                for (int nt = 0; nt < 4; nt++)
                    ldb_frag(bf[nt], sB, 136, k0l, wn * 32 + nt * 8, lane);
#pragma unroll
                for (int mt = 0; mt < 2; mt++) {
                    uint32_t af[4];
                    lda_frag(af, sU, 132, wm * 32 + mt * 16, k0u, lane);
#pragma unroll
                    for (int nt = 0; nt < 4; nt++) mma_tf32(acc2[mt][nt], af, bf[nt]);
                }
            }
        }
    }

    // ---- final epilogue: readback stash, combine, fused BN stats ----
#pragma unroll
    for (int nt = 0; nt < 4; nt++) {
        int c = wn * 32 + nt * 8 + (lane & 3) * 2;
        float g0 = gb2[c], g1 = gb2[c + 1];
        float s0 = 0.f, s1 = 0.f, q0 = 0.f, q1 = 0.f;
#pragma unroll
        for (int mt = 0; mt < 2; mt++) {
            int r = row0 + wm * 32 + mt * 16 + (lane >> 2);
            float2 stA = *(float2*)(out1 + (size_t)r * 128 + c);
            float2 stB = *(float2*)(out1 + (size_t)(r + 8) * 128 + c);
            float f0 = 0.5f * ((acc2[mt][nt][0] + g0) + stA.x);
            float f1 = 0.5f * ((acc2[mt][nt][1] + g1) + stA.y);
            float f2 = 0.5f * ((acc2[mt][nt][2] + g0) + stB.x);
            float f3 = 0.5f * ((acc2[mt][nt][3] + g1) + stB.y);
            *(float2*)(out1 + (size_t)r * 128 + c) = make_float2(f0, f1);
            *(float2*)(out1 + (size_t)(r + 8) * 128 + c) = make_float2(f2, f3);
            if (r < NN)     { s0 += f0; q0 += f0 * f0; s1 += f1; q1 += f1 * f1; }
            if (r + 8 < NN) { s0 += f2; q0 += f2 * f2; s1 += f3; q1 += f3 * f3; }
        }
#pragma unroll
        for (int off = 4; off < 32; off <<= 1) {
            s0 += __shfl_down_sync(0xffffffffu, s0, off);
            s1 += __shfl_down_sync(0xffffffffu, s1, off);
            q0 += __shfl_down_sync(0xffffffffu, q0, off);
            q1 += __shfl_down_sync(0xffffffffu, q1, off);
        }
        if ((lane >> 2) == 0) {
            atomicAdd(&g_stats[1][c], s0);
            atomicAdd(&g_stats[1][c + 1], s1);
            atomicAdd(&g_stats[1][128 + c], q0);
            atomicAdd(&g_stats[1][128 + c + 1], q1);
        }
    }
}

// ---------------- BN parameter computation (1 block) ------------------------
__global__ void bnparam_kernel(const float* __restrict__ gamma,
                               const float* __restrict__ beta) {
    int t = threadIdx.x >> 7, c = threadIdx.x & 127;
    float mu = g_stats[t][c] * (1.0f / NN);
    float var = g_stats[t][128 + c] * (1.0f / NN) - mu * mu;
    float s = gamma[c] * rsqrtf(var + 1e-5f);
    g_bnp[t][0][c] = s;
    g_bnp[t][1][c] = beta[c] - mu * s;
}

// ---------------- final BN apply (last layer, no relu) ----------------------
__global__ void bn_final_kernel(const float* __restrict__ X, int t,
                                float* __restrict__ Y) {
    __shared__ float sc[128], sh[128];
    if (threadIdx.x < 128) {
        sc[threadIdx.x] = g_bnp[t][0][threadIdx.x];
        sh[threadIdx.x] = g_bnp[t][1][threadIdx.x];
    }
    __syncthreads();
    const int total = NN * 128;
    for (int idx = blockIdx.x * blockDim.x + threadIdx.x; idx < total;
         idx += gridDim.x * blockDim.x) {
        int c = idx & 127;
        Y[idx] = fmaf(X[idx], sc[c], sh[c]);
    }
}

// ---------------- launch ----------------------------------------------------
extern "C" void kernel_launch(void* const* d_in, const int* in_sizes, int n_in,
                              void* d_out, int out_size) {
    const float* x0 = (const float*)d_in[0];
    const float* x1 = (const float*)d_in[1];
    // t0=11, t1=01, t2=10, t3=00
    const float* ea[4] = {(const float*)d_in[2], (const float*)d_in[4],
                          (const float*)d_in[3], (const float*)d_in[5]};
    const int* ei[4] = {(const int*)d_in[6], (const int*)d_in[8],
                        (const int*)d_in[7], (const int*)d_in[9]};
    const float* Wx  = (const float*)d_in[10];
    const float* bx  = (const float*)d_in[11];
    const float* We  = (const float*)d_in[12];
    const float* be  = (const float*)d_in[13];
    const float* gW1 = (const float*)d_in[14];
    const float* gb1 = (const float*)d_in[15];
    const float* gW2 = (const float*)d_in[16];
    const float* gb2 = (const float*)d_in[17];
    const float* W10 = (const float*)d_in[18];
    const float* b10 = (const float*)d_in[19];
    const float* W01 = (const float*)d_in[20];
    const float* b01 = (const float*)d_in[21];
    const float* W00 = (const float*)d_in[22];
    const float* b00 = (const float*)d_in[23];
    const float* bn_g = (const float*)d_in[24];
    const float* bn_b = (const float*)d_in[25];
    float* out = (float*)d_out;

    void *degP, *statsP, *h0P, *h1P, *nh0P, *nh1P, *bnpP;
    cudaGetSymbolAddress(&degP, g_deg);
    cudaGetSymbolAddress(&statsP, g_stats);
    cudaGetSymbolAddress(&h0P, g_h0);
    cudaGetSymbolAddress(&h1P, g_h1);
    cudaGetSymbolAddress(&nh0P, g_nh0);
    cudaGetSymbolAddress(&nh1P, g_nh1);
    cudaGetSymbolAddress(&bnpP, g_bnp);
    float* h0 = (float*)h0P;
    float* h1 = (float*)h1P;
    float* nh0 = (float*)nh0P;
    float* nh1 = (float*)nh1P;
    float* bnp0 = (float*)bnpP;
    float* bnp1 = bnp0 + 256;

    static const int C1_SMEM = (8448 + 8448 + 8704) * 4;   // 102400 B
    static const int C0_SMEM = (16640 + 8704) * 4;         // 101376 B
    cudaFuncSetAttribute(combine1_tc<false>, cudaFuncAttributeMaxDynamicSharedMemorySize, C1_SMEM);
    cudaFuncSetAttribute(combine1_tc<true>,  cudaFuncAttributeMaxDynamicSharedMemorySize, C1_SMEM);
    cudaFuncSetAttribute(combine0_tc<false>, cudaFuncAttributeMaxDynamicSharedMemorySize, C0_SMEM);
    cudaFuncSetAttribute(combine0_tc<true>,  cudaFuncAttributeMaxDynamicSharedMemorySize, C0_SMEM);

    // ---- CSR build + layer-invariant edge-attr sums ----
    cudaMemsetAsync(degP, 0, sizeof(int) * 4 * NN);
    hist_kernel<<<dim3(EE / 256, 4), 256>>>(ei[0], ei[1], ei[2], ei[3]);
    scan_kernel<<<4, 1024>>>();
    fill_kernel<<<dim3(EE / 256, 4), 256>>>(ei[0], ei[1], ei[2], ei[3]);
    ea_agg_kernel<<<dim3(NN / 16, 4), 256>>>(ea[0], ea[1], ea[2], ea[3]);

    // ---- input embeddings (tensor core) ----
    embed_tc<<<NB, 256>>>(x0, Wx, bx, h0);
    embed_tc<<<NB, 256>>>(x1, Wx, bx, h1);

    // ---- layer 0: read h0/h1, write nh0/nh1 ----
    cudaMemsetAsync(statsP, 0, sizeof(float) * 512);
    combine1_tc<false><<<NB, 256, C1_SMEM>>>(gW1, gb1, gW2, gb2, W01, b01,
                                             h1, h0, bnp1, bnp0, We, be, nh1);
    combine0_tc<false><<<NB, 256, C0_SMEM>>>(W10, b10, W00, b00,
                                             h1, h0, bnp1, bnp0, We, be, nh0);
    bnparam_kernel<<<1, 256>>>(bn_g, bn_b);

    // ---- layer 1: read nh0/nh1 (BN-relu applied on the fly), write h0/h1 ---
    cudaMemsetAsync(statsP, 0, sizeof(float) * 512);
    combine1_tc<true><<<NB, 256, C1_SMEM>>>(gW1, gb1, gW2, gb2, W01, b01,
                                            nh1, nh0, bnp1, bnp0, We, be, h1);
    combine0_tc<true><<<NB, 256, C0_SMEM>>>(W10, b10, W00, b00,
                                            nh1, nh0, bnp1, bnp0, We, be, h0);
    bnparam_kernel<<<1, 256>>>(bn_g + 128, bn_b + 128);

    // ---- final BN apply -> output ----
    bn_final_kernel<<<2048, 256>>>(h0, 0, out);
    bn_final_kernel<<<2048, 256>>>(h1, 1, out + (size_t)NN * 128);
}

// round 12
// speedup vs baseline: 1.1905x; 1.1905x over previous
#include <cuda_runtime.h>
#include <cstdint>

#define NN 100000
#define NP 100032              // padded to multiple of 64
#define EE 800000
#define NB (NP / 64)           // 1563 blocks of 64 rows

// ---------------- scratch (device globals; no allocation allowed) ----------
__device__ float g_h0[NP * 128];
__device__ float g_h1[NP * 128];
__device__ float g_nh0[NP * 128];
__device__ float g_nh1[NP * 128];
__device__ float g_agg[4][NP * 128];     // t0=11, t1=01 (dst type1), t2=10, t3=00 (dst type0)
__device__ float g_A[4][NN * 16];        // per-dst sum of raw edge attrs
__device__ int   g_deg[4][NN];
__device__ int   g_rowstart[4][NN + 1];
__device__ int   g_cursor[4][NN];
__device__ int   g_csrc[4][EE];          // CSR: src node per slot
__device__ int   g_ceid[4][EE];          // CSR: edge id per slot
__device__ float g_stats[2][256];        // [node type][ sum(128) | sumsq(128) ]
__device__ float g_bnp[2][2][128];       // [node type][ scale | shift ]

// ---------------- tf32 MMA helpers -----------------------------------------
__device__ __forceinline__ float to_tf32(float x) {
    uint32_t u;
    asm("cvt.rna.tf32.f32 %0, %1;" : "=r"(u) : "f"(x));
    return __uint_as_float(u);
}

__device__ __forceinline__ void mma_tf32(float (&d)[4], const uint32_t (&a)[4],
                                         const uint32_t (&b)[2]) {
    asm volatile(
        "mma.sync.aligned.m16n8k8.row.col.f32.tf32.tf32.f32 "
        "{%0,%1,%2,%3}, {%4,%5,%6,%7}, {%8,%9}, {%0,%1,%2,%3};"
        : "+f"(d[0]), "+f"(d[1]), "+f"(d[2]), "+f"(d[3])
        : "r"(a[0]), "r"(a[1]), "r"(a[2]), "r"(a[3]), "r"(b[0]), "r"(b[1]));
}

// A fragment from row-major smem [row][k], stride S (floats).
__device__ __forceinline__ void lda_frag(uint32_t (&af)[4], const float* sA, int S,
                                         int rbase, int k0, int lane) {
    const float* p = sA + (rbase + (lane >> 2)) * S + k0 + (lane & 3);
    af[0] = __float_as_uint(p[0]);
    af[1] = __float_as_uint(p[8 * S]);
    af[2] = __float_as_uint(p[4]);
    af[3] = __float_as_uint(p[8 * S + 4]);
}

// B fragment from smem [k][n], stride S (floats).
__device__ __forceinline__ void ldb_frag(uint32_t (&bf)[2], const float* sB, int S,
                                         int k0, int n0, int lane) {
    const float* q = sB + (k0 + (lane & 3)) * S + n0 + (lane >> 2);
    bf[0] = __float_as_uint(q[0]);
    bf[1] = __float_as_uint(q[4 * S]);
}

__device__ __forceinline__ float4 bn_relu4(float4 v, float4 sc, float4 sh) {
    v.x = fmaxf(fmaf(v.x, sc.x, sh.x), 0.f);
    v.y = fmaxf(fmaf(v.y, sc.y, sh.y), 0.f);
    v.z = fmaxf(fmaf(v.z, sc.z, sh.z), 0.f);
    v.w = fmaxf(fmaf(v.w, sc.w, sh.w), 0.f);
    return v;
}

__device__ __forceinline__ void st_tf32x4(float* d, float4 v) {
    d[0] = to_tf32(v.x); d[1] = to_tf32(v.y);
    d[2] = to_tf32(v.z); d[3] = to_tf32(v.w);
}

// ---------------- CSR build ------------------------------------------------
__global__ void hist_kernel(const int* __restrict__ e0, const int* __restrict__ e1,
                            const int* __restrict__ e2, const int* __restrict__ e3) {
    int t = blockIdx.y;
    const int* ei = (t == 0) ? e0 : (t == 1) ? e1 : (t == 2) ? e2 : e3;
    int e = blockIdx.x * blockDim.x + threadIdx.x;
    if (e < EE) atomicAdd(&g_deg[t][ei[EE + e]], 1);
}

__global__ void scan_kernel() {
    int t = blockIdx.x;
    __shared__ int sp[1024];
    int tid = threadIdx.x;
    const int chunk = (NN + 1023) / 1024;
    int start = tid * chunk;
    int end = start + chunk; if (end > NN) end = NN;
    int s = 0;
    for (int i = start; i < end; i++) s += g_deg[t][i];
    sp[tid] = s;
    __syncthreads();
    for (int off = 1; off < 1024; off <<= 1) {
        int v = (tid >= off) ? sp[tid - off] : 0;
        __syncthreads();
        sp[tid] += v;
        __syncthreads();
    }
    int run = sp[tid] - s;
    for (int i = start; i < end; i++) {
        g_rowstart[t][i] = run;
        g_cursor[t][i] = run;
        run += g_deg[t][i];
    }
    if (tid == 0) g_rowstart[t][NN] = EE;
}

__global__ void fill_kernel(const int* __restrict__ e0, const int* __restrict__ e1,
                            const int* __restrict__ e2, const int* __restrict__ e3) {
    int t = blockIdx.y;
    const int* ei = (t == 0) ? e0 : (t == 1) ? e1 : (t == 2) ? e2 : e3;
    int e = blockIdx.x * blockDim.x + threadIdx.x;
    if (e >= EE) return;
    int dst = ei[EE + e];
    int slot = atomicAdd(&g_cursor[t][dst], 1);
    g_csrc[t][slot] = ei[e];
    g_ceid[t][slot] = e;
}

// Per-dst sum of raw 16-dim edge attrs (layer-invariant). Half-warp per dst.
__global__ __launch_bounds__(256) void ea_agg_kernel(const float* __restrict__ a0,
                                                     const float* __restrict__ a1,
                                                     const float* __restrict__ a2,
                                                     const float* __restrict__ a3) {
    int t = blockIdx.y;
    const float* ea = (t == 0) ? a0 : (t == 1) ? a1 : (t == 2) ? a2 : a3;
    int lane = threadIdx.x & 31;
    int warp = threadIdx.x >> 5;
    int sub = lane >> 4;
    int l16 = lane & 15;
    int dst = blockIdx.x * 16 + warp * 2 + sub;
    if (dst >= NN) return;
    const int* __restrict__ ceid = g_ceid[t];
    int rs = g_rowstart[t][dst], re = g_rowstart[t][dst + 1];
    float acc = 0.f, accB = 0.f;
    int e = rs;
    for (; e + 4 <= re; e += 4) {
        int e0 = ceid[e], e1 = ceid[e + 1], e2 = ceid[e + 2], e3 = ceid[e + 3];
        float v0 = ea[e0 * 16 + l16];
        float v1 = ea[e1 * 16 + l16];
        float v2 = ea[e2 * 16 + l16];
        float v3 = ea[e3 * 16 + l16];
        acc += v0 + v2;
        accB += v1 + v3;
    }
    for (; e < re; e++) acc += ea[ceid[e] * 16 + l16];
    g_A[t][dst * 16 + l16] = acc + accB;
}

// ---------------- aggregation: agg = A@We + deg*be + sum f(h_src) ----------
// One launch covers all 4 edge types via blockIdx.y.
// UB: apply BN affine + relu to gathered h values (layer>=1 inputs).
template<bool UB>
__global__ __launch_bounds__(256) void agg_all_kernel(const float* __restrict__ We,
                                                      const float* __restrict__ be,
                                                      const float* __restrict__ src1,
                                                      const float* __restrict__ src0,
                                                      const float* __restrict__ bnp1,
                                                      const float* __restrict__ bnp0) {
    int t = blockIdx.y;
    const float* Hsrc = (t == 0 || t == 2) ? src1 : src0;
    const float* bnp = (t == 0 || t == 2) ? bnp1 : bnp0;
    __shared__ float sWe[16][128];
    for (int idx = threadIdx.x; idx < 2048; idx += 256)
        sWe[idx >> 7][idx & 127] = We[idx];
    __syncthreads();
    int lane = threadIdx.x & 31;
    int warp = threadIdx.x >> 5;
    int dst = blockIdx.x * 8 + warp;
    if (dst >= NN) return;
    const float4* H4 = (const float4*)Hsrc;
    int c0 = lane * 4;
    float4 sc4, sh4;
    if (UB) {
        sc4 = *(const float4*)(bnp + c0);
        sh4 = *(const float4*)(bnp + 128 + c0);
    }
    int rs = g_rowstart[t][dst], re = g_rowstart[t][dst + 1];
    float degf = (float)(re - rs);
    float4 acc = make_float4(degf * be[c0], degf * be[c0 + 1],
                             degf * be[c0 + 2], degf * be[c0 + 3]);
#pragma unroll
    for (int k = 0; k < 16; k++) {
        float a = g_A[t][dst * 16 + k];
        acc.x += a * sWe[k][c0];
        acc.y += a * sWe[k][c0 + 1];
        acc.z += a * sWe[k][c0 + 2];
        acc.w += a * sWe[k][c0 + 3];
    }
    const int* __restrict__ srcp = g_csrc[t];
    float4 acc2 = make_float4(0.f, 0.f, 0.f, 0.f);
    int e = rs;
    for (; e + 4 <= re; e += 4) {
        int s0 = srcp[e], s1 = srcp[e + 1], s2 = srcp[e + 2], s3 = srcp[e + 3];
        float4 v0 = H4[s0 * 32 + lane];
        float4 v1 = H4[s1 * 32 + lane];
        float4 v2 = H4[s2 * 32 + lane];
        float4 v3 = H4[s3 * 32 + lane];
        if (UB) {
            v0 = bn_relu4(v0, sc4, sh4); v1 = bn_relu4(v1, sc4, sh4);
            v2 = bn_relu4(v2, sc4, sh4); v3 = bn_relu4(v3, sc4, sh4);
        }
        acc.x += v0.x; acc.y += v0.y; acc.z += v0.z; acc.w += v0.w;
        acc2.x += v1.x; acc2.y += v1.y; acc2.z += v1.z; acc2.w += v1.w;
        acc.x += v2.x; acc.y += v2.y; acc.z += v2.z; acc.w += v2.w;
        acc2.x += v3.x; acc2.y += v3.y; acc2.z += v3.z; acc2.w += v3.w;
    }
    for (; e < re; e++) {
        float4 v = H4[srcp[e] * 32 + lane];
        if (UB) v = bn_relu4(v, sc4, sh4);
        acc.x += v.x; acc.y += v.y; acc.z += v.z; acc.w += v.w;
    }
    acc.x += acc2.x; acc.y += acc2.y; acc.z += acc2.z; acc.w += acc2.w;
    __stcs(((float4*)g_agg[t]) + dst * 32 + lane, acc);
}

// ---------------- embed: H = X @ Wx + bx  (grid.y picks x0->h0 / x1->h1) ----
__global__ __launch_bounds__(256) void embed_tc(const float* __restrict__ X0,
                                                const float* __restrict__ X1,
                                                const float* __restrict__ W,
                                                const float* __restrict__ bx,
                                                float* __restrict__ H0,
                                                float* __restrict__ H1) {
    const float* X = blockIdx.y ? X1 : X0;
    float* H = blockIdx.y ? H1 : H0;
    __shared__ float sA[64 * 68];    // 64 rows x 64 k, pad 4
    __shared__ float sB[64 * 136];   // 64 k x 128 n, pad 8
    int tid = threadIdx.x, lane = tid & 31, wid = tid >> 5;
    int wm = wid >> 2, wn = wid & 3;
    int row0 = blockIdx.x * 64;
    float acc[2][4][4] = {};
    float4 pa[4], pb[8];

#pragma unroll
    for (int j = 0; j < 4; j++) {
        int i = tid + j * 256, r = i >> 4, c4 = (i & 15) * 4;
        pa[j] = make_float4(0.f, 0.f, 0.f, 0.f);
        if (row0 + r < NN)
            pa[j] = *(const float4*)(X + (size_t)(row0 + r) * 256 + c4);
    }
#pragma unroll
    for (int j = 0; j < 8; j++) {
        int i = tid + j * 256, r = i >> 5, c4 = (i & 31) * 4;
        pb[j] = *(const float4*)(W + (size_t)r * 128 + c4);
    }

    for (int kc = 0; kc < 4; kc++) {
        __syncthreads();
#pragma unroll
        for (int j = 0; j < 4; j++) {
            int i = tid + j * 256, r = i >> 4, c4 = (i & 15) * 4;
            st_tf32x4(sA + r * 68 + c4, pa[j]);
        }
#pragma unroll
        for (int j = 0; j < 8; j++) {
            int i = tid + j * 256, r = i >> 5, c4 = (i & 31) * 4;
            st_tf32x4(sB + r * 136 + c4, pb[j]);
        }
        __syncthreads();
        if (kc < 3) {
            int kn = kc + 1;
#pragma unroll
            for (int j = 0; j < 4; j++) {
                int i = tid + j * 256, r = i >> 4, c4 = (i & 15) * 4;
                pa[j] = make_float4(0.f, 0.f, 0.f, 0.f);
                if (row0 + r < NN)
                    pa[j] = *(const float4*)(X + (size_t)(row0 + r) * 256 + kn * 64 + c4);
            }
#pragma unroll
            for (int j = 0; j < 8; j++) {
                int i = tid + j * 256, r = i >> 5, c4 = (i & 31) * 4;
                pb[j] = *(const float4*)(W + (size_t)(kn * 64 + r) * 128 + c4);
            }
        }
#pragma unroll
        for (int ks = 0; ks < 8; ks++) {
            int k0 = ks * 8;
            uint32_t bf[4][2];
#pragma unroll
            for (int nt = 0; nt < 4; nt++)
                ldb_frag(bf[nt], sB, 136, k0, wn * 32 + nt * 8, lane);
#pragma unroll
            for (int mt = 0; mt < 2; mt++) {
                uint32_t af[4];
                lda_frag(af, sA, 68, wm * 32 + mt * 16, k0, lane);
#pragma unroll
                for (int nt = 0; nt < 4; nt++) mma_tf32(acc[mt][nt], af, bf[nt]);
            }
        }
    }
#pragma unroll
    for (int mt = 0; mt < 2; mt++)
#pragma unroll
        for (int nt = 0; nt < 4; nt++) {
            int r = row0 + wm * 32 + mt * 16 + (lane >> 2);
            int c = wn * 32 + nt * 8 + (lane & 3) * 2;
            float b0 = bx[c], b1 = bx[c + 1];
            *(float2*)(H + (size_t)r * 128 + c) =
                make_float2(acc[mt][nt][0] + b0, acc[mt][nt][1] + b1);
            *(float2*)(H + (size_t)(r + 8) * 128 + c) =
                make_float2(acc[mt][nt][2] + b0, acc[mt][nt][3] + b1);
        }
}

// ---------------- combine0: nh0 = 0.05*(agg10@W10 + agg00@W00 + b10 + b00) --
__global__ __launch_bounds__(256) void combine0_tc(const float* __restrict__ W10,
                                                   const float* __restrict__ b10,
                                                   const float* __restrict__ W00,
                                                   const float* __restrict__ b00,
                                                   float* __restrict__ out0) {
    __shared__ float sA[64 * 68];
    __shared__ float sB[64 * 136];
    int tid = threadIdx.x, lane = tid & 31, wid = tid >> 5;
    int wm = wid >> 2, wn = wid & 3;
    int row0 = blockIdx.x * 64;
    float acc[2][4][4] = {};
    float4 pa[4], pb[8];

#pragma unroll
    for (int j = 0; j < 4; j++) {
        int i = tid + j * 256, r = i >> 4, c4 = (i & 15) * 4;
        pa[j] = __ldcs((const float4*)(g_agg[2] + (size_t)(row0 + r) * 128 + c4));
    }
#pragma unroll
    for (int j = 0; j < 8; j++) {
        int i = tid + j * 256, r = i >> 5, c4 = (i & 31) * 4;
        pb[j] = *(const float4*)(W10 + (size_t)r * 128 + c4);
    }

    for (int kc = 0; kc < 4; kc++) {
        __syncthreads();
#pragma unroll
        for (int j = 0; j < 4; j++) {
            int i = tid + j * 256, r = i >> 4, c4 = (i & 15) * 4;
            st_tf32x4(sA + r * 68 + c4, pa[j]);
        }
#pragma unroll
        for (int j = 0; j < 8; j++) {
            int i = tid + j * 256, r = i >> 5, c4 = (i & 31) * 4;
            st_tf32x4(sB + r * 136 + c4, pb[j]);
        }
        __syncthreads();
        if (kc < 3) {
            int kn = kc + 1;
            const float* Asrc = (kn < 2) ? g_agg[2] : g_agg[3];
            const float* Wsrc = (kn < 2) ? W10 : W00;
            int kb = (kn & 1) * 64;
#pragma unroll
            for (int j = 0; j < 4; j++) {
                int i = tid + j * 256, r = i >> 4, c4 = (i & 15) * 4;
                pa[j] = __ldcs((const float4*)(Asrc + (size_t)(row0 + r) * 128 + kb + c4));
            }
#pragma unroll
            for (int j = 0; j < 8; j++) {
                int i = tid + j * 256, r = i >> 5, c4 = (i & 31) * 4;
                pb[j] = *(const float4*)(Wsrc + (size_t)(kb + r) * 128 + c4);
            }
        }
#pragma unroll
        for (int ks = 0; ks < 8; ks++) {
            int k0 = ks * 8;
            uint32_t bf[4][2];
#pragma unroll
            for (int nt = 0; nt < 4; nt++)
                ldb_frag(bf[nt], sB, 136, k0, wn * 32 + nt * 8, lane);
#pragma unroll
            for (int mt = 0; mt < 2; mt++) {
                uint32_t af[4];
                lda_frag(af, sA, 68, wm * 32 + mt * 16, k0, lane);
#pragma unroll
                for (int nt = 0; nt < 4; nt++) mma_tf32(acc[mt][nt], af, bf[nt]);
            }
        }
    }
#pragma unroll
    for (int nt = 0; nt < 4; nt++) {
        int c = wn * 32 + nt * 8 + (lane & 3) * 2;
        float b0 = b10[c] + b00[c], b1 = b10[c + 1] + b00[c + 1];
        float s0 = 0.f, s1 = 0.f, q0 = 0.f, q1 = 0.f;
#pragma unroll
        for (int mt = 0; mt < 2; mt++) {
            int r = row0 + wm * 32 + mt * 16 + (lane >> 2);
            float f0 = 0.05f * (acc[mt][nt][0] + b0);
            float f1 = 0.05f * (acc[mt][nt][1] + b1);
            float f2 = 0.05f * (acc[mt][nt][2] + b0);
            float f3 = 0.05f * (acc[mt][nt][3] + b1);
            *(float2*)(out0 + (size_t)r * 128 + c) = make_float2(f0, f1);
            *(float2*)(out0 + (size_t)(r + 8) * 128 + c) = make_float2(f2, f3);
            if (r < NN)     { s0 += f0; q0 += f0 * f0; s1 += f1; q1 += f1 * f1; }
            if (r + 8 < NN) { s0 += f2; q0 += f2 * f2; s1 += f3; q1 += f3 * f3; }
        }
#pragma unroll
        for (int off = 4; off < 32; off <<= 1) {
            s0 += __shfl_down_sync(0xffffffffu, s0, off);
            s1 += __shfl_down_sync(0xffffffffu, s1, off);
            q0 += __shfl_down_sync(0xffffffffu, q0, off);
            q1 += __shfl_down_sync(0xffffffffu, q1, off);
        }
        if ((lane >> 2) == 0) {
            atomicAdd(&g_stats[0][c], s0);
            atomicAdd(&g_stats[0][c + 1], s1);
            atomicAdd(&g_stats[0][128 + c], q0);
            atomicAdd(&g_stats[0][128 + c + 1], q1);
        }
    }
}

// ---------------- combine1: GIN MLP + 0.1*linear, dst type '1' --------------
// nh1 = 0.5*( relu((agg11+1.1*f(h1))@gW1+gb1)@gW2+gb2  +  0.1*(agg01@W01+b01) )
// The 256-wide intermediate u is processed in two 128-col halves so smem fits
// 2 blocks/SM: sS 64x132, sU 64x132, sB 64x136 -> 100 KB.
__global__ __launch_bounds__(256, 2) void combine1_tc(const float* __restrict__ gW1,
                                                      const float* __restrict__ gb1,
                                                      const float* __restrict__ gW2,
                                                      const float* __restrict__ gb2,
                                                      const float* __restrict__ W01,
                                                      const float* __restrict__ b01,
                                                      const float* __restrict__ h1src,
                                                      const float* __restrict__ bnp,
                                                      float* __restrict__ out1) {
    extern __shared__ float dsm[];
    float* sS = dsm;                  // 64*132 = 8448
    float* sU = dsm + 8448;           // 64*132 = 8448
    float* sB = dsm + 16896;          // 64*136 = 8704
    int tid = threadIdx.x, lane = tid & 31, wid = tid >> 5;
    int wm = wid >> 2, wn = wid & 3;
    int row0 = blockIdx.x * 64;

    // stage sS = tf32(agg11 + 1.1*f(h1))
    for (int i = tid; i < 2048; i += 256) {
        int r = i >> 5, c4 = (i & 31) * 4;
        size_t off = (size_t)(row0 + r) * 128 + c4;
        float4 a = __ldcs((const float4*)(g_agg[0] + off));
        float4 h = *(const float4*)(h1src + off);
        if (bnp) {
            float4 sc = *(const float4*)(bnp + c4);
            float4 sh = *(const float4*)(bnp + 128 + c4);
            h = bn_relu4(h, sc, sh);
        }
        float* d = sS + r * 132 + c4;
        d[0] = to_tf32(a.x + 1.1f * h.x);
        d[1] = to_tf32(a.y + 1.1f * h.y);
        d[2] = to_tf32(a.z + 1.1f * h.z);
        d[3] = to_tf32(a.w + 1.1f * h.w);
    }

    float acc2[2][4][4] = {};   // gin accumulator, persists across both halves

    for (int nh = 0; nh < 2; nh++) {
        // ---- phase 1 (half nh): u = relu(s @ gW1[:, nh*128:+128] + gb1) ----
        float4 pb1[4];
#pragma unroll
        for (int j = 0; j < 4; j++) {
            int i = tid + j * 256, r = i >> 5, c4 = (i & 31) * 4;
            pb1[j] = *(const float4*)(gW1 + (size_t)r * 256 + nh * 128 + c4);
        }
        float acc1[2][4][4] = {};
        for (int kc = 0; kc < 4; kc++) {          // K chunks of 32
            __syncthreads();
#pragma unroll
            for (int j = 0; j < 4; j++) {
                int i = tid + j * 256, r = i >> 5, c4 = (i & 31) * 4;
                st_tf32x4(sB + r * 136 + c4, pb1[j]);
            }
            __syncthreads();
            if (kc < 3) {
                int kn = kc + 1;
#pragma unroll
                for (int j = 0; j < 4; j++) {
                    int i = tid + j * 256, r = i >> 5, c4 = (i & 31) * 4;
                    pb1[j] = *(const float4*)(gW1 + (size_t)(kn * 32 + r) * 256 + nh * 128 + c4);
                }
            }
#pragma unroll
            for (int ks = 0; ks < 4; ks++) {
                int k0g = kc * 32 + ks * 8, k0l = ks * 8;
                uint32_t bf[4][2];
#pragma unroll
                for (int nt = 0; nt < 4; nt++)
                    ldb_frag(bf[nt], sB, 136, k0l, wn * 32 + nt * 8, lane);
#pragma unroll
                for (int mt = 0; mt < 2; mt++) {
                    uint32_t af[4];
                    lda_frag(af, sS, 132, wm * 32 + mt * 16, k0g, lane);
#pragma unroll
                    for (int nt = 0; nt < 4; nt++) mma_tf32(acc1[mt][nt], af, bf[nt]);
                }
            }
        }
        // epilogue -> sU (sync: prior phase-2 reads of sU must be complete)
        __syncthreads();
#pragma unroll
        for (int mt = 0; mt < 2; mt++)
#pragma unroll
            for (int nt = 0; nt < 4; nt++) {
                int r = wm * 32 + mt * 16 + (lane >> 2);
                int c = wn * 32 + nt * 8 + (lane & 3) * 2;
                int cg = nh * 128 + c;
                float b0 = gb1[cg], b1 = gb1[cg + 1];
                float v0 = acc1[mt][nt][0] + b0; v0 = v0 > 0.f ? v0 : 0.f;
                float v1 = acc1[mt][nt][1] + b1; v1 = v1 > 0.f ? v1 : 0.f;
                float v2 = acc1[mt][nt][2] + b0; v2 = v2 > 0.f ? v2 : 0.f;
                float v3 = acc1[mt][nt][3] + b1; v3 = v3 > 0.f ? v3 : 0.f;
                sU[r * 132 + c] = to_tf32(v0);
                sU[r * 132 + c + 1] = to_tf32(v1);
                sU[(r + 8) * 132 + c] = to_tf32(v2);
                sU[(r + 8) * 132 + c + 1] = to_tf32(v3);
            }
        __syncthreads();

        // ---- phase 2 partial: acc2 += u_half @ gW2[nh*128:+128, :] ----
        float4 pb2[8];
#pragma unroll
        for (int j = 0; j < 8; j++) {
            int i = tid + j * 256, r = i >> 5, c4 = (i & 31) * 4;
            pb2[j] = *(const float4*)(gW2 + (size_t)(nh * 128 + r) * 128 + c4);
        }
        for (int kc2 = 0; kc2 < 2; kc2++) {       // K chunks of 64 within half
            __syncthreads();
#pragma unroll
            for (int j = 0; j < 8; j++) {
                int i = tid + j * 256, r = i >> 5, c4 = (i & 31) * 4;
                st_tf32x4(sB + r * 136 + c4, pb2[j]);
            }
            __syncthreads();
            if (kc2 < 1) {
#pragma unroll
                for (int j = 0; j < 8; j++) {
                    int i = tid + j * 256, r = i >> 5, c4 = (i & 31) * 4;
                    pb2[j] = *(const float4*)(gW2 + (size_t)(nh * 128 + 64 + r) * 128 + c4);
                }
            }
#pragma unroll
            for (int ks = 0; ks < 8; ks++) {
                int k0u = kc2 * 64 + ks * 8, k0l = ks * 8;
                uint32_t bf[4][2];
#pragma unroll
                for (int nt = 0; nt < 4; nt++)
                    ldb_frag(bf[nt], sB, 136, k0l, wn * 32 + nt * 8, lane);
#pragma unroll
                for (int mt = 0; mt < 2; mt++) {
                    uint32_t af[4];
                    lda_frag(af, sU, 132, wm * 32 + mt * 16, k0u, lane);
#pragma unroll
                    for (int nt = 0; nt < 4; nt++) mma_tf32(acc2[mt][nt], af, bf[nt]);
                }
            }
        }
    }

    // ---- phase 3: l01 = agg01 @ W01, [64x128]x[128x128] ----
    __syncthreads();
    for (int i = tid; i < 2048; i += 256) {   // restage sS = tf32(agg01)
        int r = i >> 5, c4 = (i & 31) * 4;
        float4 a = __ldcs((const float4*)(g_agg[1] + (size_t)(row0 + r) * 128 + c4));
        st_tf32x4(sS + r * 132 + c4, a);
    }
    float4 pb[8];
#pragma unroll
    for (int j = 0; j < 8; j++) {
        int i = tid + j * 256, r = i >> 5, c4 = (i & 31) * 4;
        pb[j] = *(const float4*)(W01 + (size_t)r * 128 + c4);
    }
    float acc3[2][4][4] = {};
    for (int kc = 0; kc < 2; kc++) {
        __syncthreads();
#pragma unroll
        for (int j = 0; j < 8; j++) {
            int i = tid + j * 256, r = i >> 5, c4 = (i & 31) * 4;
            st_tf32x4(sB + r * 136 + c4, pb[j]);
        }
        __syncthreads();
        if (kc < 1) {
#pragma unroll
            for (int j = 0; j < 8; j++) {
                int i = tid + j * 256, r = i >> 5, c4 = (i & 31) * 4;
                pb[j] = *(const float4*)(W01 + (size_t)(64 + r) * 128 + c4);
            }
        }
#pragma unroll
        for (int ks = 0; ks < 8; ks++) {
            int k0g = kc * 64 + ks * 8, k0l = ks * 8;
            uint32_t bf[4][2];
#pragma unroll
            for (int nt = 0; nt < 4; nt++)
                ldb_frag(bf[nt], sB, 136, k0l, wn * 32 + nt * 8, lane);
#pragma unroll
            for (int mt = 0; mt < 2; mt++) {
                uint32_t af[4];
                lda_frag(af, sS, 132, wm * 32 + mt * 16, k0g, lane);
#pragma unroll
                for (int nt = 0; nt < 4; nt++) mma_tf32(acc3[mt][nt], af, bf[nt]);
            }
        }
    }

    // final epilogue + fused stats
#pragma unroll
    for (int nt = 0; nt < 4; nt++) {
        int c = wn * 32 + nt * 8 + (lane & 3) * 2;
        float g0 = gb2[c], g1 = gb2[c + 1];
        float l0 = b01[c], l1 = b01[c + 1];
        float s0 = 0.f, s1 = 0.f, q0 = 0.f, q1 = 0.f;
#pragma unroll
        for (int mt = 0; mt < 2; mt++) {
            int r = row0 + wm * 32 + mt * 16 + (lane >> 2);
            float f0 = 0.5f * ((acc2[mt][nt][0] + g0) + 0.1f * (acc3[mt][nt][0] + l0));
            float f1 = 0.5f * ((acc2[mt][nt][1] + g1) + 0.1f * (acc3[mt][nt][1] + l1));
            float f2 = 0.5f * ((acc2[mt][nt][2] + g0) + 0.1f * (acc3[mt][nt][2] + l0));
            float f3 = 0.5f * ((acc2[mt][nt][3] + g1) + 0.1f * (acc3[mt][nt][3] + l1));
            *(float2*)(out1 + (size_t)r * 128 + c) = make_float2(f0, f1);
            *(float2*)(out1 + (size_t)(r + 8) * 128 + c) = make_float2(f2, f3);
            if (r < NN)     { s0 += f0; q0 += f0 * f0; s1 += f1; q1 += f1 * f1; }
            if (r + 8 < NN) { s0 += f2; q0 += f2 * f2; s1 += f3; q1 += f3 * f3; }
        }
#pragma unroll
        for (int off = 4; off < 32; off <<= 1) {
            s0 += __shfl_down_sync(0xffffffffu, s0, off);
            s1 += __shfl_down_sync(0xffffffffu, s1, off);
            q0 += __shfl_down_sync(0xffffffffu, q0, off);
            q1 += __shfl_down_sync(0xffffffffu, q1, off);
        }
        if ((lane >> 2) == 0) {
            atomicAdd(&g_stats[1][c], s0);
            atomicAdd(&g_stats[1][c + 1], s1);
            atomicAdd(&g_stats[1][128 + c], q0);
            atomicAdd(&g_stats[1][128 + c + 1], q1);
        }
    }
}

// ---------------- BN parameter computation (1 block) ------------------------
__global__ void bnparam_kernel(const float* __restrict__ gamma,
                               const float* __restrict__ beta) {
    int t = threadIdx.x >> 7, c = threadIdx.x & 127;
    float mu = g_stats[t][c] * (1.0f / NN);
    float var = g_stats[t][128 + c] * (1.0f / NN) - mu * mu;
    float s = gamma[c] * rsqrtf(var + 1e-5f);
    g_bnp[t][0][c] = s;
    g_bnp[t][1][c] = beta[c] - mu * s;
}

// ---------------- final BN apply (last layer, no relu; grid.y = node type) --
__global__ void bn_final_kernel(const float* __restrict__ X0,
                                const float* __restrict__ X1,
                                float* __restrict__ Y) {
    int t = blockIdx.y;
    const float* X = t ? X1 : X0;
    float* Yt = Y + (size_t)t * NN * 128;
    __shared__ float sc[128], sh[128];
    if (threadIdx.x < 128) {
        sc[threadIdx.x] = g_bnp[t][0][threadIdx.x];
        sh[threadIdx.x] = g_bnp[t][1][threadIdx.x];
    }
    __syncthreads();
    const int total = NN * 128;
    for (int idx = blockIdx.x * blockDim.x + threadIdx.x; idx < total;
         idx += gridDim.x * blockDim.x) {
        int c = idx & 127;
        Yt[idx] = fmaf(X[idx], sc[c], sh[c]);
    }
}

// ---------------- launch ----------------------------------------------------
extern "C" void kernel_launch(void* const* d_in, const int* in_sizes, int n_in,
                              void* d_out, int out_size) {
    const float* x0 = (const float*)d_in[0];
    const float* x1 = (const float*)d_in[1];
    // t0=11, t1=01, t2=10, t3=00
    const float* ea[4] = {(const float*)d_in[2], (const float*)d_in[4],
                          (const float*)d_in[3], (const float*)d_in[5]};
    const int* ei[4] = {(const int*)d_in[6], (const int*)d_in[8],
                        (const int*)d_in[7], (const int*)d_in[9]};
    const float* Wx  = (const float*)d_in[10];
    const float* bx  = (const float*)d_in[11];
    const float* We  = (const float*)d_in[12];
    const float* be  = (const float*)d_in[13];
    const float* gW1 = (const float*)d_in[14];
    const float* gb1 = (const float*)d_in[15];
    const float* gW2 = (const float*)d_in[16];
    const float* gb2 = (const float*)d_in[17];
    const float* W10 = (const float*)d_in[18];
    const float* b10 = (const float*)d_in[19];
    const float* W01 = (const float*)d_in[20];
    const float* b01 = (const float*)d_in[21];
    const float* W00 = (const float*)d_in[22];
    const float* b00 = (const float*)d_in[23];
    const float* bn_g = (const float*)d_in[24];
    const float* bn_b = (const float*)d_in[25];
    float* out = (float*)d_out;

    void *degP, *statsP, *h0P, *h1P, *nh0P, *nh1P, *bnpP;
    cudaGetSymbolAddress(&degP, g_deg);
    cudaGetSymbolAddress(&statsP, g_stats);
    cudaGetSymbolAddress(&h0P, g_h0);
    cudaGetSymbolAddress(&h1P, g_h1);
    cudaGetSymbolAddress(&nh0P, g_nh0);
    cudaGetSymbolAddress(&nh1P, g_nh1);
    cudaGetSymbolAddress(&bnpP, g_bnp);
    float* h0 = (float*)h0P;
    float* h1 = (float*)h1P;
    float* nh0 = (float*)nh0P;
    float* nh1 = (float*)nh1P;
    float* bnp0 = (float*)bnpP;
    float* bnp1 = bnp0 + 256;

    static const int C1_SMEM = (8448 + 8448 + 8704) * 4;   // 102400 B
    cudaFuncSetAttribute(combine1_tc, cudaFuncAttributeMaxDynamicSharedMemorySize, C1_SMEM);

    // ---- CSR build + layer-invariant edge-attr sums ----
    cudaMemsetAsync(degP, 0, sizeof(int) * 4 * NN);
    hist_kernel<<<dim3(EE / 256, 4), 256>>>(ei[0], ei[1], ei[2], ei[3]);
    scan_kernel<<<4, 1024>>>();
    fill_kernel<<<dim3(EE / 256, 4), 256>>>(ei[0], ei[1], ei[2], ei[3]);
    ea_agg_kernel<<<dim3(NN / 16, 4), 256>>>(ea[0], ea[1], ea[2], ea[3]);

    // ---- input embeddings (tensor core, both node types in one launch) ----
    embed_tc<<<dim3(NB, 2), 256>>>(x0, x1, Wx, bx, h0, h1);

    // ---- layer 0 (reads raw embeddings; BN folded into layer-1 consumers) --
    cudaMemsetAsync(statsP, 0, sizeof(float) * 512);
    agg_all_kernel<false><<<dim3(NN / 8, 4), 256>>>(We, be, h1, h0, nullptr, nullptr);
    combine1_tc<<<NB, 256, C1_SMEM>>>(gW1, gb1, gW2, gb2, W01, b01, h1, nullptr, nh1);
    combine0_tc<<<NB, 256>>>(W10, b10, W00, b00, nh0);
    bnparam_kernel<<<1, 256>>>(bn_g, bn_b);

    // ---- layer 1 (consumers apply layer-0 BN affine + relu on the fly) -----
    cudaMemsetAsync(statsP, 0, sizeof(float) * 512);
    agg_all_kernel<true><<<dim3(NN / 8, 4), 256>>>(We, be, nh1, nh0, bnp1, bnp0);
    combine1_tc<<<NB, 256, C1_SMEM>>>(gW1, gb1, gW2, gb2, W01, b01, nh1, bnp1, h1);
    combine0_tc<<<NB, 256>>>(W10, b10, W00, b00, h0);
    bnparam_kernel<<<1, 256>>>(bn_g + 128, bn_b + 128);

    // ---- final BN apply -> output ----
    bn_final_kernel<<<dim3(1024, 2), 256>>>(h0, h1, out);
}